// round 8
// baseline (speedup 1.0000x reference)
#include <cuda_runtime.h>
#include <cuda_bf16.h>
#include <cstdint>

// Problem constants
#define NROWS     8192
#define KDIM      1024
#define SHORTLIST 4000
#define C1HI      20000
#define NCLASSES  50257
#define HEADC     4002

// Tile config (bf16): stage = K=64 slab
#define TM 128
#define TN 128
#define NSTG 4
#define KSTG 16                                  // 1024 / 64
#define STAGE_BYTES (TM*128 + TN*128)            // 16KB A + 16KB B
#define SMEM_TOTAL  (1024 + NSTG*STAGE_BYTES + 512)

// flat-grid decode
#define HEAD_CTAS (64*32)            // 2048
#define C1_CTAS   (64*125)           // 8000
#define C2_CTAS   (64*237)           // 15168
#define TOTAL_CTAS (HEAD_CTAS + C1_CTAS + C2_CTAS)

// ---------------- scratch ----------------------------------------------------
#define IN_ELEMS (NROWS*KDIM)
#define W_ELEMS  (NCLASSES*KDIM)
#define T_ELEMS  (2*KDIM)
__device__ __nv_bfloat16 g_ibf[IN_ELEMS];
__device__ __nv_bfloat16 g_wbf[W_ELEMS];
__device__ __nv_bfloat16 g_tbf[T_ELEMS];

__device__ float g_head_sum[NROWS];
__device__ float g_tail_sum[NROWS];
__device__ float g_head_gath[NROWS];
__device__ float g_targ_logit[NROWS];
__device__ int   g_rows[2][NROWS];
__device__ int   g_cnt[2];
__device__ float g_loss;

__device__ __forceinline__ int cluster_of(int t) {
    return (t < SHORTLIST) ? 0 : ((t < C1HI) ? 1 : 2);
}
__device__ __forceinline__ uint32_t smem_u32(const void* p) {
    uint32_t a;
    asm("{ .reg .u64 t; cvta.to.shared.u64 t, %1; cvt.u32.u64 %0, t; }" : "=r"(a) : "l"(p));
    return a;
}
#define CP16(dst, src) \
    asm volatile("cp.async.cg.shared.global [%0], [%1], 16;" :: "r"(dst), "l"(src) : "memory")
#define CP_COMMIT() asm volatile("cp.async.commit_group;" ::: "memory")

#define LDSM4(r, a) \
    asm volatile("ldmatrix.sync.aligned.m8n8.x4.shared.b16 {%0,%1,%2,%3}, [%4];" \
                 : "=r"((r)[0]), "=r"((r)[1]), "=r"((r)[2]), "=r"((r)[3]) : "r"(a))

#define MMA_BF16(c, a, b0, b1) \
    asm volatile("mma.sync.aligned.m16n8k16.row.col.f32.bf16.bf16.f32 " \
                 "{%0,%1,%2,%3}, {%4,%5,%6,%7}, {%8,%9}, {%0,%1,%2,%3};" \
                 : "+f"((c)[0]), "+f"((c)[1]), "+f"((c)[2]), "+f"((c)[3]) \
                 : "r"((a)[0]), "r"((a)[1]), "r"((a)[2]), "r"((a)[3]), "r"(b0), "r"(b1))

// ---------------- init / compact / convert -----------------------------------
__global__ void init_kernel() {
    int i = blockIdx.x * blockDim.x + threadIdx.x;
    if (i < NROWS) { g_head_sum[i] = 0.f; g_tail_sum[i] = 0.f; }
    if (i == 0) { g_cnt[0] = 0; g_cnt[1] = 0; g_loss = 0.f; }
}
__global__ void compact_kernel(const int* __restrict__ target) {
    int i = blockIdx.x * blockDim.x + threadIdx.x;
    if (i >= NROWS) return;
    int c = cluster_of(target[i]);
    if (c > 0) {
        int p = atomicAdd(&g_cnt[c - 1], 1);
        g_rows[c - 1][p] = i;
    }
}
// fp32 -> bf16 for input, weight, tail_vectors (float4 -> 4x bf16 per thread)
__global__ void convert_kernel(const float* __restrict__ in,
                               const float* __restrict__ w,
                               const float* __restrict__ tv) {
    long long i4 = (long long)blockIdx.x * blockDim.x + threadIdx.x;
    const long long nin = IN_ELEMS / 4, nw = W_ELEMS / 4, nt = T_ELEMS / 4;
    const float4* src; __nv_bfloat16* dst; long long off;
    if (i4 < nin)                { src = (const float4*)in; dst = g_ibf; off = i4; }
    else if (i4 < nin + nw)      { src = (const float4*)w;  dst = g_wbf; off = i4 - nin; }
    else if (i4 < nin + nw + nt) { src = (const float4*)tv; dst = g_tbf; off = i4 - nin - nw; }
    else return;
    float4 v = src[off];
    __nv_bfloat162 lo = __floats2bfloat162_rn(v.x, v.y);
    __nv_bfloat162 hi = __floats2bfloat162_rn(v.z, v.w);
    uint2 pk;
    pk.x = *(uint32_t*)&lo;
    pk.y = *(uint32_t*)&hi;
    *(uint2*)&dst[off * 4] = pk;
}

// ---------------- fused bf16 tensor GEMM + sum(exp) + gather -----------------
// One flat grid: [0,2048) head | [2048,10048) cluster1 | [10048,25216) cluster2
__global__ __launch_bounds__(256, 1)
void tc_gemm_lse(const int*   __restrict__ target,
                 const float* __restrict__ bias,
                 const float* __restrict__ tailb)
{
    extern __shared__ char smem[];

    int bid = blockIdx.x;
    int mode, by, bx, nrows, collo, colhi;
    const int* rowlist;
    if (bid < HEAD_CTAS) {
        mode = 0; by = bid & 63; bx = bid >> 6;
        nrows = NROWS; collo = 0; colhi = HEADC; rowlist = nullptr;
    } else if (bid < HEAD_CTAS + C1_CTAS) {
        int t = bid - HEAD_CTAS;
        mode = 1; by = t & 63; bx = t >> 6;
        nrows = g_cnt[0]; collo = SHORTLIST; colhi = C1HI; rowlist = g_rows[0];
    } else {
        int t = bid - HEAD_CTAS - C1_CTAS;
        mode = 2; by = t & 63; bx = t >> 6;
        nrows = g_cnt[1]; collo = C1HI; colhi = NCLASSES; rowlist = g_rows[1];
    }
    if (by * TM >= nrows) return;

    const int tid = threadIdx.x;
    const int wid = tid >> 5;
    const int lid = tid & 31;
    const int wm  = wid >> 2;
    const int wn  = wid & 3;

    uint32_t sb     = smem_u32(smem);
    uint32_t stage0 = (sb + 1023) & ~1023u;
    float* bias_sm  = (float*)(smem + (stage0 - sb) + NSTG * STAGE_BYTES);

    if (tid < TN) {
        int gcol = collo + bx * TN + tid;
        float bb = 0.f;
        if (mode == 0) {
            if (gcol < SHORTLIST)  bb = bias[gcol];
            else if (gcol < HEADC) bb = tailb[gcol - SHORTLIST];
        } else if (gcol < colhi)   bb = bias[gcol];
        bias_sm[tid] = bb;
    }

    // load plan: 8 x 16B chunks/thread/stage (16B = 8 bf16 = k8)
    const __nv_bfloat16* asrc[4]; uint32_t adst[4];
    const __nv_bfloat16* bsrc[4]; uint32_t bdst[4];
    #pragma unroll
    for (int i = 0; i < 4; i++) {
        int id  = tid + i * 256;
        int row = id >> 3, c = id & 7;
        int grow = by * TM + row;
        int arow = (grow < nrows) ? (rowlist ? rowlist[grow] : grow) : 0;
        asrc[i]  = g_ibf + (size_t)arow * KDIM + c * 8;
        adst[i]  = row * 128 + ((c * 16) ^ ((row & 7) * 16));
        int gcol = collo + bx * TN + row;
        const __nv_bfloat16* bp;
        if (mode == 0) {
            if (gcol < SHORTLIST)   bp = g_wbf + (size_t)gcol * KDIM;
            else if (gcol < HEADC)  bp = g_tbf + (size_t)(gcol - SHORTLIST) * KDIM;
            else                    bp = g_wbf;               // dup, masked later
        } else {
            int bc = gcol < colhi ? gcol : (colhi - 1);
            bp = g_wbf + (size_t)bc * KDIM;
        }
        bsrc[i] = bp + c * 8;
        bdst[i] = TM * 128 + row * 128 + ((c * 16) ^ ((row & 7) * 16));
    }

    // ldmatrix lane constants (identical chunk math to tf32: 16B chunks)
    const int a_rin = (lid & 7) | (((lid >> 3) & 1) << 3);
    const int a_chi = (lid >> 4) & 1;
    const int b_nin = (lid & 7) | (((lid >> 4) & 1) << 3);
    const int b_chi = (lid >> 3) & 1;
    const uint32_t xv = (lid & 7) * 16;

    uint32_t arow_off[4], brow_off[2];
    #pragma unroll
    for (int mi = 0; mi < 4; mi++) arow_off[mi] = (wm * 64 + mi * 16 + a_rin) * 128;
    #pragma unroll
    for (int g = 0; g < 2; g++)    brow_off[g]  = TM * 128 + (wn * 32 + g * 16 + b_nin) * 128;

    // prologue: NSTG-1 stages in flight
    #pragma unroll
    for (int s = 0; s < NSTG - 1; s++) {
        uint32_t base = stage0 + s * STAGE_BYTES;
        #pragma unroll
        for (int i = 0; i < 4; i++) CP16(base + adst[i], asrc[i] + s * 64);
        #pragma unroll
        for (int i = 0; i < 4; i++) CP16(base + bdst[i], bsrc[i] + s * 64);
        CP_COMMIT();
    }

    float acc[4][4][4] = {};

    // main loop: 16 K-slabs of 64, single sync per iteration
    for (int s = 0; s < KSTG; s++) {
        uint32_t sbuf = stage0 + (s % NSTG) * STAGE_BYTES;
        if (s <= KSTG - 3)      asm volatile("cp.async.wait_group 2;" ::: "memory");
        else if (s == KSTG - 2) asm volatile("cp.async.wait_group 1;" ::: "memory");
        else                    asm volatile("cp.async.wait_group 0;" ::: "memory");
        __syncthreads();

        // prefetch stage s+NSTG-1 into the buffer freed at iteration s-1
        if (s + NSTG - 1 < KSTG) {
            uint32_t pbuf = stage0 + ((s + NSTG - 1) % NSTG) * STAGE_BYTES;
            int k0 = (s + NSTG - 1) * 64;
            #pragma unroll
            for (int i = 0; i < 4; i++) CP16(pbuf + adst[i], asrc[i] + k0);
            #pragma unroll
            for (int i = 0; i < 4; i++) CP16(pbuf + bdst[i], bsrc[i] + k0);
            CP_COMMIT();
        }

        #pragma unroll
        for (int ks = 0; ks < 4; ks++) {            // 4 x k16 per slab
            uint32_t af[4][4], bf[2][4];
            uint32_t asw = (uint32_t)((ks * 2 + a_chi) * 16) ^ xv;
            uint32_t bsw = (uint32_t)((ks * 2 + b_chi) * 16) ^ xv;
            #pragma unroll
            for (int mi = 0; mi < 4; mi++) LDSM4(af[mi], sbuf + arow_off[mi] + asw);
            #pragma unroll
            for (int g = 0; g < 2; g++)    LDSM4(bf[g],  sbuf + brow_off[g]  + bsw);
            #pragma unroll
            for (int mi = 0; mi < 4; mi++)
                #pragma unroll
                for (int ni = 0; ni < 4; ni++)
                    MMA_BF16(acc[mi][ni], af[mi], bf[ni >> 1][(ni & 1) * 2],
                                                   bf[ni >> 1][(ni & 1) * 2 + 1]);
        }
    }

    // epilogue: bias + exp + row-sum + target gather (fp32)
    float* sumdst = (mode == 0) ? g_head_sum : g_tail_sum;
    float* gatdst = (mode == 0) ? g_head_gath : g_targ_logit;

    #pragma unroll
    for (int mi = 0; mi < 4; mi++) {
        int tr0 = wm * 64 + mi * 16 + (lid >> 2);
        int grow0 = by * TM + tr0, grow1 = grow0 + 8;
        bool v0 = grow0 < nrows, v1 = grow1 < nrows;
        int orow0 = 0, orow1 = 0, gidx0 = -1, gidx1 = -1;
        if (v0) {
            orow0 = rowlist ? rowlist[grow0] : grow0;
            int t = target[orow0];
            gidx0 = (mode == 0) ? ((t < SHORTLIST) ? t : (SHORTLIST + cluster_of(t) - 1)) : t;
        }
        if (v1) {
            orow1 = rowlist ? rowlist[grow1] : grow1;
            int t = target[orow1];
            gidx1 = (mode == 0) ? ((t < SHORTLIST) ? t : (SHORTLIST + cluster_of(t) - 1)) : t;
        }
        float s0 = 0.f, s1 = 0.f, gl0 = 0.f, gl1 = 0.f;
        bool f0 = false, f1 = false;
        #pragma unroll
        for (int ni = 0; ni < 4; ni++) {
            int cbase = wn * 32 + ni * 8 + 2 * (lid & 3);
            #pragma unroll
            for (int h = 0; h < 2; h++) {
                int col = cbase + h;
                int gcol = collo + bx * TN + col;
                if (gcol < colhi) {
                    float bb = bias_sm[col];
                    float l0 = acc[mi][ni][h]     + bb;
                    float l1 = acc[mi][ni][2 + h] + bb;
                    s0 += __expf(l0);
                    s1 += __expf(l1);
                    if (gcol == gidx0) { gl0 = l0; f0 = true; }
                    if (gcol == gidx1) { gl1 = l1; f1 = true; }
                }
            }
        }
        s0 += __shfl_xor_sync(0xffffffffu, s0, 1);
        s0 += __shfl_xor_sync(0xffffffffu, s0, 2);
        s1 += __shfl_xor_sync(0xffffffffu, s1, 1);
        s1 += __shfl_xor_sync(0xffffffffu, s1, 2);
        if ((lid & 3) == 0) {
            if (v0) atomicAdd(&sumdst[orow0], s0);
            if (v1) atomicAdd(&sumdst[orow1], s1);
        }
        if (f0 && v0) gatdst[orow0] = gl0;
        if (f1 && v1) gatdst[orow1] = gl1;
    }
}

// ---------------- finalize ----------------------------------------------------
__global__ void finalize_kernel(const int* __restrict__ target,
                                float* __restrict__ out)
{
    __shared__ float red[256];
    int i = blockIdx.x * 256 + threadIdx.x;
    float neg = 0.f;
    if (i < NROWS) {
        int cid = cluster_of(target[i]);
        float res = g_head_gath[i] - logf(g_head_sum[i]);
        if (cid > 0) res += g_targ_logit[i] - logf(g_tail_sum[i]);
        out[i] = res;
        neg = -res;
    }
    red[threadIdx.x] = neg;
    __syncthreads();
    #pragma unroll
    for (int s2 = 128; s2 > 0; s2 >>= 1) {
        if (threadIdx.x < s2) red[threadIdx.x] += red[threadIdx.x + s2];
        __syncthreads();
    }
    if (threadIdx.x == 0) atomicAdd(&g_loss, red[0]);
}
__global__ void write_loss_kernel(float* __restrict__ out, int out_size) {
    if (out_size > NROWS) out[NROWS] = g_loss / (float)NROWS;
}

// ---------------- launch ------------------------------------------------------
extern "C" void kernel_launch(void* const* d_in, const int* in_sizes, int n_in,
                              void* d_out, int out_size) {
    const float* input  = (const float*)d_in[0];
    const int*   target = (const int*)  d_in[1];
    const float* weight = (const float*)d_in[2];
    const float* bias   = (const float*)d_in[3];
    const float* tailv  = (const float*)d_in[4];
    const float* tailb  = (const float*)d_in[5];
    float* out = (float*)d_out;

    cudaFuncSetAttribute(tc_gemm_lse, cudaFuncAttributeMaxDynamicSharedMemorySize, SMEM_TOTAL);

    init_kernel<<<NROWS / 256, 256>>>();
    compact_kernel<<<NROWS / 256, 256>>>(target);

    long long n4 = (long long)IN_ELEMS / 4 + W_ELEMS / 4 + T_ELEMS / 4;
    convert_kernel<<<(int)((n4 + 255) / 256), 256>>>(input, weight, tailv);

    tc_gemm_lse<<<TOTAL_CTAS, 256, SMEM_TOTAL>>>(target, bias, tailb);

    finalize_kernel<<<NROWS / 256, 256>>>(target, out);
    write_loss_kernel<<<1, 1>>>(out, out_size);
}

// round 9
// speedup vs baseline: 1.7978x; 1.7978x over previous
#include <cuda_runtime.h>
#include <cuda_bf16.h>
#include <cstdint>

// Problem constants
#define NROWS     8192
#define KDIM      1024
#define SHORTLIST 4000
#define C1HI      20000
#define NCLASSES  50257
#define HEADC     4002

// Tile config (bf16): stage = K=64 slab, 512 threads / 16 warps
#define TM 128
#define TN 128
#define NSTG 4
#define KSTG 16                                  // 1024 / 64
#define STAGE_BYTES (TM*128 + TN*128)            // 16KB A + 16KB B
#define SMEM_TOTAL  (1024 + NSTG*STAGE_BYTES + 512)
#define NTHREADS 512

// flat-grid decode
#define HEAD_CTAS (64*32)            // 2048
#define C1_CTAS   (64*125)           // 8000
#define C2_CTAS   (64*237)           // 15168
#define TOTAL_CTAS (HEAD_CTAS + C1_CTAS + C2_CTAS)

// ---------------- scratch ----------------------------------------------------
#define IN_ELEMS (NROWS*KDIM)
#define W_ELEMS  (NCLASSES*KDIM)
#define T_ELEMS  (2*KDIM)
__device__ __nv_bfloat16 g_ibf[IN_ELEMS];
__device__ __nv_bfloat16 g_wbf[W_ELEMS];
__device__ __nv_bfloat16 g_tbf[T_ELEMS];

__device__ float g_head_sum[NROWS];
__device__ float g_tail_sum[NROWS];
__device__ float g_head_gath[NROWS];
__device__ float g_targ_logit[NROWS];
__device__ int   g_rows[2][NROWS];
__device__ int   g_cnt[2];
__device__ float g_loss;

__device__ __forceinline__ int cluster_of(int t) {
    return (t < SHORTLIST) ? 0 : ((t < C1HI) ? 1 : 2);
}
__device__ __forceinline__ uint32_t smem_u32(const void* p) {
    uint32_t a;
    asm("{ .reg .u64 t; cvta.to.shared.u64 t, %1; cvt.u32.u64 %0, t; }" : "=r"(a) : "l"(p));
    return a;
}
#define CP16(dst, src) \
    asm volatile("cp.async.cg.shared.global [%0], [%1], 16;" :: "r"(dst), "l"(src) : "memory")
#define CP_COMMIT() asm volatile("cp.async.commit_group;" ::: "memory")

#define LDSM4(r, a) \
    asm volatile("ldmatrix.sync.aligned.m8n8.x4.shared.b16 {%0,%1,%2,%3}, [%4];" \
                 : "=r"((r)[0]), "=r"((r)[1]), "=r"((r)[2]), "=r"((r)[3]) : "r"(a))

#define MMA_BF16(c, a, b0, b1) \
    asm volatile("mma.sync.aligned.m16n8k16.row.col.f32.bf16.bf16.f32 " \
                 "{%0,%1,%2,%3}, {%4,%5,%6,%7}, {%8,%9}, {%0,%1,%2,%3};" \
                 : "+f"((c)[0]), "+f"((c)[1]), "+f"((c)[2]), "+f"((c)[3]) \
                 : "r"((a)[0]), "r"((a)[1]), "r"((a)[2]), "r"((a)[3]), "r"(b0), "r"(b1))

// ---------------- init / compact / convert -----------------------------------
__global__ void init_kernel() {
    int i = blockIdx.x * blockDim.x + threadIdx.x;
    if (i < NROWS) { g_head_sum[i] = 0.f; g_tail_sum[i] = 0.f; }
    if (i == 0) { g_cnt[0] = 0; g_cnt[1] = 0; g_loss = 0.f; }
}
__global__ void compact_kernel(const int* __restrict__ target) {
    int i = blockIdx.x * blockDim.x + threadIdx.x;
    if (i >= NROWS) return;
    int c = cluster_of(target[i]);
    if (c > 0) {
        int p = atomicAdd(&g_cnt[c - 1], 1);
        g_rows[c - 1][p] = i;
    }
}
__global__ void convert_kernel(const float* __restrict__ in,
                               const float* __restrict__ w,
                               const float* __restrict__ tv) {
    long long i4 = (long long)blockIdx.x * blockDim.x + threadIdx.x;
    const long long nin = IN_ELEMS / 4, nw = W_ELEMS / 4, nt = T_ELEMS / 4;
    const float4* src; __nv_bfloat16* dst; long long off;
    if (i4 < nin)                { src = (const float4*)in; dst = g_ibf; off = i4; }
    else if (i4 < nin + nw)      { src = (const float4*)w;  dst = g_wbf; off = i4 - nin; }
    else if (i4 < nin + nw + nt) { src = (const float4*)tv; dst = g_tbf; off = i4 - nin - nw; }
    else return;
    float4 v = src[off];
    __nv_bfloat162 lo = __floats2bfloat162_rn(v.x, v.y);
    __nv_bfloat162 hi = __floats2bfloat162_rn(v.z, v.w);
    uint2 pk;
    pk.x = *(uint32_t*)&lo;
    pk.y = *(uint32_t*)&hi;
    *(uint2*)&dst[off * 4] = pk;
}

// ---------------- fused bf16 tensor GEMM + sum(exp) + gather -----------------
// Flat grid: [0,2048) head | [2048,10048) cluster1 | [10048,25216) cluster2
// 512 threads, 16 warps in 4x4: warp tile 32 rows x 32 cols.
__global__ __launch_bounds__(NTHREADS, 1)
void tc_gemm_lse(const int*   __restrict__ target,
                 const float* __restrict__ bias,
                 const float* __restrict__ tailb)
{
    extern __shared__ char smem[];

    int bid = blockIdx.x;
    int mode, by, bx, nrows, collo, colhi;
    const int* rowlist;
    if (bid < HEAD_CTAS) {
        mode = 0; by = bid & 63; bx = bid >> 6;
        nrows = NROWS; collo = 0; colhi = HEADC; rowlist = nullptr;
    } else if (bid < HEAD_CTAS + C1_CTAS) {
        int t = bid - HEAD_CTAS;
        mode = 1; by = t & 63; bx = t >> 6;
        nrows = g_cnt[0]; collo = SHORTLIST; colhi = C1HI; rowlist = g_rows[0];
    } else {
        int t = bid - HEAD_CTAS - C1_CTAS;
        mode = 2; by = t & 63; bx = t >> 6;
        nrows = g_cnt[1]; collo = C1HI; colhi = NCLASSES; rowlist = g_rows[1];
    }
    if (by * TM >= nrows) return;

    const int tid = threadIdx.x;
    const int wid = tid >> 5;
    const int lid = tid & 31;
    const int wm  = wid >> 2;    // 0..3 -> rows wm*32
    const int wn  = wid & 3;     // 0..3 -> cols wn*32

    uint32_t sb     = smem_u32(smem);
    uint32_t stage0 = (sb + 1023) & ~1023u;
    float* bias_sm  = (float*)(smem + (stage0 - sb) + NSTG * STAGE_BYTES);

    if (tid < TN) {
        int gcol = collo + bx * TN + tid;
        float bb = 0.f;
        if (mode == 0) {
            if (gcol < SHORTLIST)  bb = bias[gcol];
            else if (gcol < HEADC) bb = tailb[gcol - SHORTLIST];
        } else if (gcol < colhi)   bb = bias[gcol];
        bias_sm[tid] = bb;
    }

    // load plan: 4 x 16B chunks/thread/stage (2 A + 2 B); 16B = 8 bf16 = k8
    const __nv_bfloat16* asrc[2]; uint32_t adst[2];
    const __nv_bfloat16* bsrc[2]; uint32_t bdst[2];
    #pragma unroll
    for (int i = 0; i < 2; i++) {
        int id  = tid + i * NTHREADS;     // 0..1023
        int row = id >> 3, c = id & 7;
        int grow = by * TM + row;
        int arow = (grow < nrows) ? (rowlist ? rowlist[grow] : grow) : 0;
        asrc[i]  = g_ibf + (size_t)arow * KDIM + c * 8;
        adst[i]  = row * 128 + ((c * 16) ^ ((row & 7) * 16));
        int gcol = collo + bx * TN + row;
        const __nv_bfloat16* bp;
        if (mode == 0) {
            if (gcol < SHORTLIST)   bp = g_wbf + (size_t)gcol * KDIM;
            else if (gcol < HEADC)  bp = g_tbf + (size_t)(gcol - SHORTLIST) * KDIM;
            else                    bp = g_wbf;               // dup, masked later
        } else {
            int bc = gcol < colhi ? gcol : (colhi - 1);
            bp = g_wbf + (size_t)bc * KDIM;
        }
        bsrc[i] = bp + c * 8;
        bdst[i] = TM * 128 + row * 128 + ((c * 16) ^ ((row & 7) * 16));
    }

    // ldmatrix lane constants (16B-chunk math)
    const int a_rin = (lid & 7) | (((lid >> 3) & 1) << 3);
    const int a_chi = (lid >> 4) & 1;
    const int b_nin = (lid & 7) | (((lid >> 4) & 1) << 3);
    const int b_chi = (lid >> 3) & 1;
    const uint32_t xv = (lid & 7) * 16;

    uint32_t arow_off[2], brow_off[2];
    #pragma unroll
    for (int mi = 0; mi < 2; mi++) arow_off[mi] = (wm * 32 + mi * 16 + a_rin) * 128;
    #pragma unroll
    for (int g = 0; g < 2; g++)    brow_off[g]  = TM * 128 + (wn * 32 + g * 16 + b_nin) * 128;

    // prologue: NSTG-1 stages in flight
    #pragma unroll
    for (int s = 0; s < NSTG - 1; s++) {
        uint32_t base = stage0 + s * STAGE_BYTES;
        #pragma unroll
        for (int i = 0; i < 2; i++) CP16(base + adst[i], asrc[i] + s * 64);
        #pragma unroll
        for (int i = 0; i < 2; i++) CP16(base + bdst[i], bsrc[i] + s * 64);
        CP_COMMIT();
    }

    float acc[2][4][4] = {};

    // main loop: 16 K-slabs of 64, one sync per slab
    for (int s = 0; s < KSTG; s++) {
        uint32_t sbuf = stage0 + (s % NSTG) * STAGE_BYTES;
        if (s <= KSTG - 3)      asm volatile("cp.async.wait_group 2;" ::: "memory");
        else if (s == KSTG - 2) asm volatile("cp.async.wait_group 1;" ::: "memory");
        else                    asm volatile("cp.async.wait_group 0;" ::: "memory");
        __syncthreads();

        if (s + NSTG - 1 < KSTG) {
            uint32_t pbuf = stage0 + ((s + NSTG - 1) % NSTG) * STAGE_BYTES;
            int k0 = (s + NSTG - 1) * 64;
            #pragma unroll
            for (int i = 0; i < 2; i++) CP16(pbuf + adst[i], asrc[i] + k0);
            #pragma unroll
            for (int i = 0; i < 2; i++) CP16(pbuf + bdst[i], bsrc[i] + k0);
            CP_COMMIT();
        }

        #pragma unroll
        for (int ks = 0; ks < 4; ks++) {            // 4 x k16 per slab
            uint32_t af[2][4], bf[2][4];
            uint32_t asw = (uint32_t)((ks * 2 + a_chi) * 16) ^ xv;
            uint32_t bsw = (uint32_t)((ks * 2 + b_chi) * 16) ^ xv;
            #pragma unroll
            for (int mi = 0; mi < 2; mi++) LDSM4(af[mi], sbuf + arow_off[mi] + asw);
            #pragma unroll
            for (int g = 0; g < 2; g++)    LDSM4(bf[g],  sbuf + brow_off[g]  + bsw);
            #pragma unroll
            for (int mi = 0; mi < 2; mi++)
                #pragma unroll
                for (int ni = 0; ni < 4; ni++)
                    MMA_BF16(acc[mi][ni], af[mi], bf[ni >> 1][(ni & 1) * 2],
                                                   bf[ni >> 1][(ni & 1) * 2 + 1]);
        }
    }

    // epilogue: bias + exp + row-sum + target gather (fp32)
    float* sumdst = (mode == 0) ? g_head_sum : g_tail_sum;
    float* gatdst = (mode == 0) ? g_head_gath : g_targ_logit;

    #pragma unroll
    for (int mi = 0; mi < 2; mi++) {
        int tr0 = wm * 32 + mi * 16 + (lid >> 2);
        int grow0 = by * TM + tr0, grow1 = grow0 + 8;
        bool v0 = grow0 < nrows, v1 = grow1 < nrows;
        int orow0 = 0, orow1 = 0, gidx0 = -1, gidx1 = -1;
        if (v0) {
            orow0 = rowlist ? rowlist[grow0] : grow0;
            int t = target[orow0];
            gidx0 = (mode == 0) ? ((t < SHORTLIST) ? t : (SHORTLIST + cluster_of(t) - 1)) : t;
        }
        if (v1) {
            orow1 = rowlist ? rowlist[grow1] : grow1;
            int t = target[orow1];
            gidx1 = (mode == 0) ? ((t < SHORTLIST) ? t : (SHORTLIST + cluster_of(t) - 1)) : t;
        }
        float s0 = 0.f, s1 = 0.f, gl0 = 0.f, gl1 = 0.f;
        bool f0 = false, f1 = false;
        #pragma unroll
        for (int ni = 0; ni < 4; ni++) {
            int cbase = wn * 32 + ni * 8 + 2 * (lid & 3);
            #pragma unroll
            for (int h = 0; h < 2; h++) {
                int col = cbase + h;
                int gcol = collo + bx * TN + col;
                if (gcol < colhi) {
                    float bb = bias_sm[col];
                    float l0 = acc[mi][ni][h]     + bb;
                    float l1 = acc[mi][ni][2 + h] + bb;
                    s0 += __expf(l0);
                    s1 += __expf(l1);
                    if (gcol == gidx0) { gl0 = l0; f0 = true; }
                    if (gcol == gidx1) { gl1 = l1; f1 = true; }
                }
            }
        }
        s0 += __shfl_xor_sync(0xffffffffu, s0, 1);
        s0 += __shfl_xor_sync(0xffffffffu, s0, 2);
        s1 += __shfl_xor_sync(0xffffffffu, s1, 1);
        s1 += __shfl_xor_sync(0xffffffffu, s1, 2);
        if ((lid & 3) == 0) {
            if (v0) atomicAdd(&sumdst[orow0], s0);
            if (v1) atomicAdd(&sumdst[orow1], s1);
        }
        if (f0 && v0) gatdst[orow0] = gl0;
        if (f1 && v1) gatdst[orow1] = gl1;
    }
}

// ---------------- finalize ----------------------------------------------------
__global__ void finalize_kernel(const int* __restrict__ target,
                                float* __restrict__ out)
{
    __shared__ float red[256];
    int i = blockIdx.x * 256 + threadIdx.x;
    float neg = 0.f;
    if (i < NROWS) {
        int cid = cluster_of(target[i]);
        float res = g_head_gath[i] - logf(g_head_sum[i]);
        if (cid > 0) res += g_targ_logit[i] - logf(g_tail_sum[i]);
        out[i] = res;
        neg = -res;
    }
    red[threadIdx.x] = neg;
    __syncthreads();
    #pragma unroll
    for (int s2 = 128; s2 > 0; s2 >>= 1) {
        if (threadIdx.x < s2) red[threadIdx.x] += red[threadIdx.x + s2];
        __syncthreads();
    }
    if (threadIdx.x == 0) atomicAdd(&g_loss, red[0]);
}
__global__ void write_loss_kernel(float* __restrict__ out, int out_size) {
    if (out_size > NROWS) out[NROWS] = g_loss / (float)NROWS;
}

// ---------------- launch ------------------------------------------------------
extern "C" void kernel_launch(void* const* d_in, const int* in_sizes, int n_in,
                              void* d_out, int out_size) {
    const float* input  = (const float*)d_in[0];
    const int*   target = (const int*)  d_in[1];
    const float* weight = (const float*)d_in[2];
    const float* bias   = (const float*)d_in[3];
    const float* tailv  = (const float*)d_in[4];
    const float* tailb  = (const float*)d_in[5];
    float* out = (float*)d_out;

    cudaFuncSetAttribute(tc_gemm_lse, cudaFuncAttributeMaxDynamicSharedMemorySize, SMEM_TOTAL);

    init_kernel<<<NROWS / 256, 256>>>();
    compact_kernel<<<NROWS / 256, 256>>>(target);

    long long n4 = (long long)IN_ELEMS / 4 + W_ELEMS / 4 + T_ELEMS / 4;
    convert_kernel<<<(int)((n4 + 255) / 256), 256>>>(input, weight, tailv);

    tc_gemm_lse<<<TOTAL_CTAS, NTHREADS, SMEM_TOTAL>>>(target, bias, tailb);

    finalize_kernel<<<NROWS / 256, 256>>>(target, out);
    write_loss_kernel<<<1, 1>>>(out, out_size);
}

// round 14
// speedup vs baseline: 2.4784x; 1.3786x over previous
#include <cuda_runtime.h>
#include <cuda_bf16.h>
#include <cstdint>

// Problem constants
#define NROWS     8192
#define KDIM      1024
#define SHORTLIST 4000
#define C1HI      20000
#define NCLASSES  50257
#define HEADC     4002

// Tile config (bf16): CTA 128x128, 256 threads / 8 warps in 4x2 (warp tile 32x64)
// 2 CTAs per SM -> 16 warps/SM, NSTG=3 so 2x smem fits.
#define TM 128
#define TN 128
#define NSTG 3
#define KSTG 16                                  // 1024 / 64 (K=64 per slab)
#define STAGE_BYTES (TM*128 + TN*128)            // 16KB A + 16KB B
#define SMEM_TOTAL  (1024 + NSTG*STAGE_BYTES + 512)
#define NTHREADS 256

// flat-grid decode
#define HEAD_CTAS (64*32)            // 2048
#define C1_CTAS   (64*125)           // 8000
#define C2_CTAS   (64*237)           // 15168
#define TOTAL_CTAS (HEAD_CTAS + C1_CTAS + C2_CTAS)

// ---------------- scratch ----------------------------------------------------
#define IN_ELEMS (NROWS*KDIM)
#define W_ELEMS  (NCLASSES*KDIM)
#define T_ELEMS  (2*KDIM)
__device__ __nv_bfloat16 g_ibf[IN_ELEMS];
__device__ __nv_bfloat16 g_wbf[W_ELEMS];
__device__ __nv_bfloat16 g_tbf[T_ELEMS];

__device__ float g_head_sum[NROWS];
__device__ float g_tail_sum[NROWS];
__device__ float g_head_gath[NROWS];
__device__ float g_targ_logit[NROWS];
__device__ int   g_rows[2][NROWS];
__device__ int   g_cnt[2];
__device__ float g_loss;

__device__ __forceinline__ int cluster_of(int t) {
    return (t < SHORTLIST) ? 0 : ((t < C1HI) ? 1 : 2);
}
__device__ __forceinline__ uint32_t smem_u32(const void* p) {
    uint32_t a;
    asm("{ .reg .u64 t; cvta.to.shared.u64 t, %1; cvt.u32.u64 %0, t; }" : "=r"(a) : "l"(p));
    return a;
}
#define CP16(dst, src) \
    asm volatile("cp.async.cg.shared.global [%0], [%1], 16;" :: "r"(dst), "l"(src) : "memory")
#define CP_COMMIT() asm volatile("cp.async.commit_group;" ::: "memory")

#define LDSM4(r, a) \
    asm volatile("ldmatrix.sync.aligned.m8n8.x4.shared.b16 {%0,%1,%2,%3}, [%4];" \
                 : "=r"((r)[0]), "=r"((r)[1]), "=r"((r)[2]), "=r"((r)[3]) : "r"(a))

#define MMA_BF16(c, a, b0, b1) \
    asm volatile("mma.sync.aligned.m16n8k16.row.col.f32.bf16.bf16.f32 " \
                 "{%0,%1,%2,%3}, {%4,%5,%6,%7}, {%8,%9}, {%0,%1,%2,%3};" \
                 : "+f"((c)[0]), "+f"((c)[1]), "+f"((c)[2]), "+f"((c)[3]) \
                 : "r"((a)[0]), "r"((a)[1]), "r"((a)[2]), "r"((a)[3]), "r"(b0), "r"(b1))

// ---------------- init / compact / convert -----------------------------------
__global__ void init_kernel() {
    int i = blockIdx.x * blockDim.x + threadIdx.x;
    if (i < NROWS) { g_head_sum[i] = 0.f; g_tail_sum[i] = 0.f; }
    if (i == 0) { g_cnt[0] = 0; g_cnt[1] = 0; g_loss = 0.f; }
}
__global__ void compact_kernel(const int* __restrict__ target) {
    int i = blockIdx.x * blockDim.x + threadIdx.x;
    if (i >= NROWS) return;
    int c = cluster_of(target[i]);
    if (c > 0) {
        int p = atomicAdd(&g_cnt[c - 1], 1);
        g_rows[c - 1][p] = i;
    }
}
__global__ void convert_kernel(const float* __restrict__ in,
                               const float* __restrict__ w,
                               const float* __restrict__ tv) {
    long long i4 = (long long)blockIdx.x * blockDim.x + threadIdx.x;
    const long long nin = IN_ELEMS / 4, nw = W_ELEMS / 4, nt = T_ELEMS / 4;
    const float4* src; __nv_bfloat16* dst; long long off;
    if (i4 < nin)                { src = (const float4*)in; dst = g_ibf; off = i4; }
    else if (i4 < nin + nw)      { src = (const float4*)w;  dst = g_wbf; off = i4 - nin; }
    else if (i4 < nin + nw + nt) { src = (const float4*)tv; dst = g_tbf; off = i4 - nin - nw; }
    else return;
    float4 v = src[off];
    __nv_bfloat162 lo = __floats2bfloat162_rn(v.x, v.y);
    __nv_bfloat162 hi = __floats2bfloat162_rn(v.z, v.w);
    uint2 pk;
    pk.x = *(uint32_t*)&lo;
    pk.y = *(uint32_t*)&hi;
    *(uint2*)&dst[off * 4] = pk;
}

// ---------------- fused bf16 tensor GEMM + sum(exp) + gather -----------------
// Flat grid: [0,2048) head | [2048,10048) cluster1 | [10048,25216) cluster2
// 8 warps in 4x2: warp tile 32 rows x 64 cols (A dup x2, B dup x4).
__global__ __launch_bounds__(NTHREADS, 2)
void tc_gemm_lse(const int*   __restrict__ target,
                 const float* __restrict__ bias,
                 const float* __restrict__ tailb)
{
    extern __shared__ char smem[];

    int bid = blockIdx.x;
    int mode, by, bx, nrows, collo, colhi;
    const int* rowlist;
    if (bid < HEAD_CTAS) {
        mode = 0; by = bid & 63; bx = bid >> 6;
        nrows = NROWS; collo = 0; colhi = HEADC; rowlist = nullptr;
    } else if (bid < HEAD_CTAS + C1_CTAS) {
        int t = bid - HEAD_CTAS;
        mode = 1; by = t & 63; bx = t >> 6;
        nrows = g_cnt[0]; collo = SHORTLIST; colhi = C1HI; rowlist = g_rows[0];
    } else {
        int t = bid - HEAD_CTAS - C1_CTAS;
        mode = 2; by = t & 63; bx = t >> 6;
        nrows = g_cnt[1]; collo = C1HI; colhi = NCLASSES; rowlist = g_rows[1];
    }
    if (by * TM >= nrows) return;

    const int tid = threadIdx.x;
    const int wid = tid >> 5;
    const int lid = tid & 31;
    const int wm  = wid >> 1;    // 0..3 -> rows wm*32
    const int wn  = wid & 1;     // 0..1 -> cols wn*64

    uint32_t sb     = smem_u32(smem);
    uint32_t stage0 = (sb + 1023) & ~1023u;
    float* bias_sm  = (float*)(smem + (stage0 - sb) + NSTG * STAGE_BYTES);

    if (tid < TN) {
        int gcol = collo + bx * TN + tid;
        float bb = 0.f;
        if (mode == 0) {
            if (gcol < SHORTLIST)  bb = bias[gcol];
            else if (gcol < HEADC) bb = tailb[gcol - SHORTLIST];
        } else if (gcol < colhi)   bb = bias[gcol];
        bias_sm[tid] = bb;
    }

    // load plan: 8 x 16B chunks/thread/stage (4 A + 4 B); 16B = 8 bf16 = k8
    const __nv_bfloat16* asrc[4]; uint32_t adst[4];
    const __nv_bfloat16* bsrc[4]; uint32_t bdst[4];
    #pragma unroll
    for (int i = 0; i < 4; i++) {
        int id  = tid + i * NTHREADS;     // 0..1023
        int row = id >> 3, c = id & 7;
        int grow = by * TM + row;
        int arow = (grow < nrows) ? (rowlist ? rowlist[grow] : grow) : 0;
        asrc[i]  = g_ibf + (size_t)arow * KDIM + c * 8;
        adst[i]  = row * 128 + ((c * 16) ^ ((row & 7) * 16));
        int gcol = collo + bx * TN + row;
        const __nv_bfloat16* bp;
        if (mode == 0) {
            if (gcol < SHORTLIST)   bp = g_wbf + (size_t)gcol * KDIM;
            else if (gcol < HEADC)  bp = g_tbf + (size_t)(gcol - SHORTLIST) * KDIM;
            else                    bp = g_wbf;               // dup, masked later
        } else {
            int bc = gcol < colhi ? gcol : (colhi - 1);
            bp = g_wbf + (size_t)bc * KDIM;
        }
        bsrc[i] = bp + c * 8;
        bdst[i] = TM * 128 + row * 128 + ((c * 16) ^ ((row & 7) * 16));
    }

    // ldmatrix lane constants (16B-chunk math)
    const int a_rin = (lid & 7) | (((lid >> 3) & 1) << 3);
    const int a_chi = (lid >> 4) & 1;
    const int b_nin = (lid & 7) | (((lid >> 4) & 1) << 3);
    const int b_chi = (lid >> 3) & 1;
    const uint32_t xv = (lid & 7) * 16;

    uint32_t arow_off[2], brow_off[4];
    #pragma unroll
    for (int mi = 0; mi < 2; mi++) arow_off[mi] = (wm * 32 + mi * 16 + a_rin) * 128;
    #pragma unroll
    for (int g = 0; g < 4; g++)    brow_off[g]  = TM * 128 + (wn * 64 + g * 16 + b_nin) * 128;

    // prologue: NSTG-1 stages in flight
    #pragma unroll
    for (int s = 0; s < NSTG - 1; s++) {
        uint32_t base = stage0 + s * STAGE_BYTES;
        #pragma unroll
        for (int i = 0; i < 4; i++) CP16(base + adst[i], asrc[i] + s * 64);
        #pragma unroll
        for (int i = 0; i < 4; i++) CP16(base + bdst[i], bsrc[i] + s * 64);
        CP_COMMIT();
    }

    float acc[2][8][4] = {};     // [mi][ni][frag], warp tile 32x64

    // main loop: 16 K-slabs of 64, one sync per slab
    for (int s = 0; s < KSTG; s++) {
        uint32_t sbuf = stage0 + (s % NSTG) * STAGE_BYTES;
        if (s < KSTG - 1) asm volatile("cp.async.wait_group 1;" ::: "memory");
        else              asm volatile("cp.async.wait_group 0;" ::: "memory");
        __syncthreads();

        if (s + NSTG - 1 < KSTG) {
            uint32_t pbuf = stage0 + ((s + NSTG - 1) % NSTG) * STAGE_BYTES;
            int k0 = (s + NSTG - 1) * 64;
            #pragma unroll
            for (int i = 0; i < 4; i++) CP16(pbuf + adst[i], asrc[i] + k0);
            #pragma unroll
            for (int i = 0; i < 4; i++) CP16(pbuf + bdst[i], bsrc[i] + k0);
            CP_COMMIT();
        }

        #pragma unroll
        for (int ks = 0; ks < 4; ks++) {            // 4 x k16 per slab
            uint32_t af[2][4], bf[4][4];
            uint32_t asw = (uint32_t)((ks * 2 + a_chi) * 16) ^ xv;
            uint32_t bsw = (uint32_t)((ks * 2 + b_chi) * 16) ^ xv;
            #pragma unroll
            for (int mi = 0; mi < 2; mi++) LDSM4(af[mi], sbuf + arow_off[mi] + asw);
            #pragma unroll
            for (int g = 0; g < 4; g++)    LDSM4(bf[g],  sbuf + brow_off[g]  + bsw);
            #pragma unroll
            for (int mi = 0; mi < 2; mi++)
                #pragma unroll
                for (int ni = 0; ni < 8; ni++)
                    MMA_BF16(acc[mi][ni], af[mi], bf[ni >> 1][(ni & 1) * 2],
                                                   bf[ni >> 1][(ni & 1) * 2 + 1]);
        }
    }

    // epilogue: bias + exp + row-sum + target gather (fp32)
    float* sumdst = (mode == 0) ? g_head_sum : g_tail_sum;
    float* gatdst = (mode == 0) ? g_head_gath : g_targ_logit;

    #pragma unroll
    for (int mi = 0; mi < 2; mi++) {
        int tr0 = wm * 32 + mi * 16 + (lid >> 2);
        int grow0 = by * TM + tr0, grow1 = grow0 + 8;
        bool v0 = grow0 < nrows, v1 = grow1 < nrows;
        int orow0 = 0, orow1 = 0, gidx0 = -1, gidx1 = -1;
        if (v0) {
            orow0 = rowlist ? rowlist[grow0] : grow0;
            int t = target[orow0];
            gidx0 = (mode == 0) ? ((t < SHORTLIST) ? t : (SHORTLIST + cluster_of(t) - 1)) : t;
        }
        if (v1) {
            orow1 = rowlist ? rowlist[grow1] : grow1;
            int t = target[orow1];
            gidx1 = (mode == 0) ? ((t < SHORTLIST) ? t : (SHORTLIST + cluster_of(t) - 1)) : t;
        }
        float s0 = 0.f, s1 = 0.f, gl0 = 0.f, gl1 = 0.f;
        bool f0 = false, f1 = false;
        #pragma unroll
        for (int ni = 0; ni < 8; ni++) {
            int cbase = wn * 64 + ni * 8 + 2 * (lid & 3);
            #pragma unroll
            for (int h = 0; h < 2; h++) {
                int col = cbase + h;
                int gcol = collo + bx * TN + col;
                if (gcol < colhi) {
                    float bb = bias_sm[col];
                    float l0 = acc[mi][ni][h]     + bb;
                    float l1 = acc[mi][ni][2 + h] + bb;
                    s0 += __expf(l0);
                    s1 += __expf(l1);
                    if (gcol == gidx0) { gl0 = l0; f0 = true; }
                    if (gcol == gidx1) { gl1 = l1; f1 = true; }
                }
            }
        }
        s0 += __shfl_xor_sync(0xffffffffu, s0, 1);
        s0 += __shfl_xor_sync(0xffffffffu, s0, 2);
        s1 += __shfl_xor_sync(0xffffffffu, s1, 1);
        s1 += __shfl_xor_sync(0xffffffffu, s1, 2);
        if ((lid & 3) == 0) {
            if (v0) atomicAdd(&sumdst[orow0], s0);
            if (v1) atomicAdd(&sumdst[orow1], s1);
        }
        if (f0 && v0) gatdst[orow0] = gl0;
        if (f1 && v1) gatdst[orow1] = gl1;
    }
}

// ---------------- finalize ----------------------------------------------------
__global__ void finalize_kernel(const int* __restrict__ target,
                                float* __restrict__ out)
{
    __shared__ float red[256];
    int i = blockIdx.x * 256 + threadIdx.x;
    float neg = 0.f;
    if (i < NROWS) {
        int cid = cluster_of(target[i]);
        float res = g_head_gath[i] - logf(g_head_sum[i]);
        if (cid > 0) res += g_targ_logit[i] - logf(g_tail_sum[i]);
        out[i] = res;
        neg = -res;
    }
    red[threadIdx.x] = neg;
    __syncthreads();
    #pragma unroll
    for (int s2 = 128; s2 > 0; s2 >>= 1) {
        if (threadIdx.x < s2) red[threadIdx.x] += red[threadIdx.x + s2];
        __syncthreads();
    }
    if (threadIdx.x == 0) atomicAdd(&g_loss, red[0]);
}
__global__ void write_loss_kernel(float* __restrict__ out, int out_size) {
    if (out_size > NROWS) out[NROWS] = g_loss / (float)NROWS;
}

// ---------------- launch ------------------------------------------------------
extern "C" void kernel_launch(void* const* d_in, const int* in_sizes, int n_in,
                              void* d_out, int out_size) {
    const float* input  = (const float*)d_in[0];
    const int*   target = (const int*)  d_in[1];
    const float* weight = (const float*)d_in[2];
    const float* bias   = (const float*)d_in[3];
    const float* tailv  = (const float*)d_in[4];
    const float* tailb  = (const float*)d_in[5];
    float* out = (float*)d_out;

    cudaFuncSetAttribute(tc_gemm_lse, cudaFuncAttributeMaxDynamicSharedMemorySize, SMEM_TOTAL);

    init_kernel<<<NROWS / 256, 256>>>();
    compact_kernel<<<NROWS / 256, 256>>>(target);

    long long n4 = (long long)IN_ELEMS / 4 + W_ELEMS / 4 + T_ELEMS / 4;
    convert_kernel<<<(int)((n4 + 255) / 256), 256>>>(input, weight, tailv);

    tc_gemm_lse<<<TOTAL_CTAS, NTHREADS, SMEM_TOTAL>>>(target, bias, tailb);

    finalize_kernel<<<NROWS / 256, 256>>>(target, out);
    write_loss_kernel<<<1, 1>>>(out, out_size);
}